// round 12
// baseline (speedup 1.0000x reference)
#include <cuda_runtime.h>
#include <cuda_bf16.h>
#include <mma.h>
#include <math.h>

using namespace nvcuda;

// ---------------- problem constants ----------------
#define BSZ   64
#define HID   512
#define G3    1536
#define LEN   400
#define TOUT  100
#define VOC   50000
#define LMAX  400
#define MROWS (TOUT*BSZ)
#define NCB   391           // phase-C column blocks: ceil(50000/128)
#define KDIM  512
#define NB2   32
#define TB2   384

// ---------------- device scratch ----------------
__device__ float g_encGx[(size_t)LEN*BSZ*G3];
__device__ float g_attnx[(size_t)TOUT*BSZ*LMAX];
__device__ float g_combx[(size_t)TOUT*BSZ*HID];
__device__ int   g_dectok[TOUT*BSZ];
__device__ float g_h[BSZ*HID];
__device__ __nv_bfloat16 g_hbf[BSZ*HID];
__device__ __nv_bfloat16 g_cbf[BSZ*HID];
__device__ float g_enc0[BSZ*HID];
__device__ float g_enc0W[BSZ*HID];
__device__ float g_a0[BSZ];
__device__ __nv_bfloat16 g_H2bf[(size_t)MROWS*HID];
__device__ __nv_bfloat16 g_embbf[(size_t)VOC*HID];
__device__ __nv_bfloat16 g_Wobf[(size_t)VOC*HID];
__device__ __nv_bfloat16 g_Wihbf[(size_t)G3*HID];
__device__ __nv_bfloat16 g_Whhbf[(size_t)G3*HID];
__device__ __nv_bfloat16 g_dWihbf[(size_t)G3*HID];
__device__ __nv_bfloat16 g_dWhhbf[(size_t)G3*HID];
__device__ float g_pm[(size_t)MROWS*NCB];
__device__ float g_ps[(size_t)MROWS*NCB];
__device__ float g_tgtlog[MROWS];
__device__ float g_lossp[32];

__device__ unsigned g_barcnt;
__device__ unsigned g_bargen;

__device__ __forceinline__ float sigmf(float x) { return 1.0f / (1.0f + expf(-x)); }

__device__ __forceinline__ void gridbar32(unsigned &gen)
{
    __syncthreads();
    if (threadIdx.x == 0) {
        __threadfence();
        unsigned prev = atomicAdd(&g_barcnt, 1u);
        if (prev == NB2 - 1u) {
            atomicExch(&g_barcnt, 0u);
            __threadfence();
            atomicAdd(&g_bargen, 1u);
        } else {
            while (atomicAdd(&g_bargen, 0u) == gen) __nanosleep(32);
        }
        gen++;
    }
    __syncthreads();
}

// ---------------- fp32 -> bf16 conversion ----------------
__global__ void k_tobf(const float* __restrict__ s, __nv_bfloat16* __restrict__ d, int n)
{
    int i = (blockIdx.x * 256 + threadIdx.x) << 2;
    if (i < n) {
        float4 v = *(const float4*)(s + i);
        *(__nv_bfloat162*)(d + i)     = __floats2bfloat162_rn(v.x, v.y);
        *(__nv_bfloat162*)(d + i + 2) = __floats2bfloat162_rn(v.z, v.w);
    }
}

__global__ void k_init(const int* __restrict__ tgt)
{
    int i = blockIdx.x * 256 + threadIdx.x;
    if (i < BSZ*HID) {
        g_h[i] = 0.0f;
        g_hbf[i] = __float2bfloat16(0.0f);
    }
    if (i < TOUT*BSZ) {
        int t = i / BSZ, b = i % BSZ;
        g_dectok[i] = (t == 0) ? 1 : tgt[(t-1)*BSZ + b];
    }
}

// ================= bf16 WMMA GEMM, 128x128 block, K=512, double-buffered =================
template<int MODE>
__global__ void __launch_bounds__(256)
k_wgemm(const __nv_bfloat16* __restrict__ Abf,
        const int* __restrict__ gidx,
        const __nv_bfloat16* __restrict__ Bbf,
        const float* __restrict__ bias,
        float* __restrict__ Cout, int ldC,
        const int* __restrict__ tgt,
        int Ncols)
{
    __shared__ __align__(16) char sbuf[40960];
    float* sC = (float*)sbuf;

    const int tid  = threadIdx.x;
    const int warp = tid >> 5;
    const int rt = warp & 3;
    const int cn = warp >> 2;
    const int bm = blockIdx.y * 128;
    const int bn = blockIdx.x * 128;

    const int cr = tid >> 2;
    const int q8 = (tid & 3) << 3;

    size_t ga0, ga1;
    if (MODE == 0) {
        ga0 = (size_t)gidx[bm + cr]      * KDIM + q8;
        ga1 = (size_t)gidx[bm + cr + 64] * KDIM + q8;
    } else {
        ga0 = (size_t)(bm + cr)      * KDIM + q8;
        ga1 = (size_t)(bm + cr + 64) * KDIM + q8;
    }
    int nb0 = bn + cr;      if (nb0 >= Ncols) nb0 = Ncols - 1;
    int nb1 = bn + cr + 64; if (nb1 >= Ncols) nb1 = Ncols - 1;
    size_t gb0 = (size_t)nb0 * KDIM + q8;
    size_t gb1 = (size_t)nb1 * KDIM + q8;

    const int sa0 = cr*40 + q8;
    const int sa1 = sa0 + 64*40;

    __nv_bfloat16* bufA[2] = { (__nv_bfloat16*)sbuf, (__nv_bfloat16*)(sbuf + 20480) };
    __nv_bfloat16* bufB[2] = { (__nv_bfloat16*)(sbuf + 10240), (__nv_bfloat16*)(sbuf + 30720) };

    uint4 rA0 = *(const uint4*)(Abf + ga0);
    uint4 rA1 = *(const uint4*)(Abf + ga1);
    uint4 rB0 = *(const uint4*)(Bbf + gb0);
    uint4 rB1 = *(const uint4*)(Bbf + gb1);
    *(uint4*)(bufA[0] + sa0) = rA0;
    *(uint4*)(bufA[0] + sa1) = rA1;
    *(uint4*)(bufB[0] + sa0) = rB0;
    *(uint4*)(bufB[0] + sa1) = rB1;
    __syncthreads();

    wmma::fragment<wmma::accumulator, 16, 16, 16, float> fc[2][4];
    for (int mi = 0; mi < 2; mi++)
        for (int ni = 0; ni < 4; ni++)
            wmma::fill_fragment(fc[mi][ni], 0.0f);

    for (int it = 0; it < 16; it++) {
        if (it < 15) {
            int kg = (it + 1) * 32;
            rA0 = *(const uint4*)(Abf + ga0 + kg);
            rA1 = *(const uint4*)(Abf + ga1 + kg);
            rB0 = *(const uint4*)(Bbf + gb0 + kg);
            rB1 = *(const uint4*)(Bbf + gb1 + kg);
        }
        __nv_bfloat16* cA = bufA[it & 1];
        __nv_bfloat16* cB = bufB[it & 1];
        for (int kk = 0; kk < 32; kk += 16) {
            wmma::fragment<wmma::matrix_a, 16, 16, 16, __nv_bfloat16, wmma::row_major> fa[2];
            wmma::fragment<wmma::matrix_b, 16, 16, 16, __nv_bfloat16, wmma::col_major> fb[4];
            wmma::load_matrix_sync(fa[0], cA + (rt*32     )*40 + kk, 40);
            wmma::load_matrix_sync(fa[1], cA + (rt*32 + 16)*40 + kk, 40);
            for (int ni = 0; ni < 4; ni++)
                wmma::load_matrix_sync(fb[ni], cB + (cn*64 + ni*16)*40 + kk, 40);
            for (int mi = 0; mi < 2; mi++)
                for (int ni = 0; ni < 4; ni++)
                    wmma::mma_sync(fc[mi][ni], fa[mi], fb[ni], fc[mi][ni]);
        }
        if (it < 15) {
            __nv_bfloat16* nA = bufA[(it + 1) & 1];
            __nv_bfloat16* nB = bufB[(it + 1) & 1];
            *(uint4*)(nA + sa0) = rA0;
            *(uint4*)(nA + sa1) = rA1;
            *(uint4*)(nB + sa0) = rB0;
            *(uint4*)(nB + sa1) = rB1;
        }
        __syncthreads();
    }

    if (MODE == 0) {
        for (int mi = 0; mi < 2; mi++)
            for (int ni = 0; ni < 4; ni++) {
                size_t row = bm + rt*32 + mi*16;
                int col = bn + cn*64 + ni*16;
                wmma::store_matrix_sync(Cout + row * (size_t)ldC + col,
                                        fc[mi][ni], ldC, wmma::mem_row_major);
            }
    } else {
        const int r  = tid >> 1;
        const int hf = tid & 1;
        const int rg = bm + r;
        const int tv = tgt[rg];
        float Mrun = -1e30f, Srun = 0.0f;

        for (int h = 0; h < 2; h++) {
            if (cn == h) {
                for (int mi = 0; mi < 2; mi++)
                    for (int ni = 0; ni < 4; ni++)
                        wmma::store_matrix_sync(sC + (rt*32 + mi*16)*72 + ni*16,
                                                fc[mi][ni], 72, wmma::mem_row_major);
            }
            __syncthreads();

            float* crow = sC + r*72 + hf*32;
            int cbase = bn + h*64 + hf*32;
            float mx = -1e30f;
            for (int c = 0; c < 32; c++) {
                int gc = cbase + c;
                float v = (gc < Ncols) ? (crow[c] + bias[gc]) : -1e30f;
                crow[c] = v;
                mx = fmaxf(mx, v);
            }
            float s = 0.0f;
            for (int c = 0; c < 32; c++) s += expf(crow[c] - mx);

            float mo = __shfl_xor_sync(0xffffffffu, mx, 1);
            float so = __shfl_xor_sync(0xffffffffu, s,  1);
            float M2 = fmaxf(mx, mo);
            float S2 = s * expf(mx - M2) + so * expf(mo - M2);

            int lc = tv - cbase;
            if (lc >= 0 && lc < 32) g_tgtlog[rg] = crow[lc];

            float nm = fmaxf(Mrun, M2);
            Srun = Srun * expf(Mrun - nm) + S2 * expf(M2 - nm);
            Mrun = nm;
            __syncthreads();
        }
        if (hf == 0) {
            g_pm[(size_t)rg * NCB + blockIdx.x] = Mrun;
            g_ps[(size_t)rg * NCB + blockIdx.x] = Srun;
        }
    }
}

// ---------------- generic fp32 SGEMM (small phase-A ops) ----------------
template<bool GATHER>
__global__ void __launch_bounds__(256)
k_sgemm128(const float* __restrict__ A,
           const int*  __restrict__ gidx,
           const float* __restrict__ Bw, int ldb,
           const float* __restrict__ bias,
           float* __restrict__ C,
           int M, int N, int K)
{
    __shared__ __align__(16) float sA[16][128];
    __shared__ __align__(16) float sB[16][128];
    const int tid = threadIdx.x;
    const int bm = blockIdx.y * 128;
    const int bn = blockIdx.x * 128;
    const int tx = tid & 15;
    const int ty = tid >> 4;
    const int lr = tid >> 2;
    const int lk = (tid & 3) << 2;

    int m0 = bm + lr, m1 = m0 + 64;
    const bool mv0 = m0 < M, mv1 = m1 < M;
    size_t ar0, ar1;
    if (GATHER) {
        ar0 = (size_t)(mv0 ? gidx[m0] : gidx[0]) * (size_t)K;
        ar1 = (size_t)(mv1 ? gidx[m1] : gidx[0]) * (size_t)K;
    } else {
        ar0 = (size_t)(mv0 ? m0 : 0) * (size_t)K;
        ar1 = (size_t)(mv1 ? m1 : 0) * (size_t)K;
    }
    int n0 = bn + lr, n1 = n0 + 64;
    size_t br0 = (size_t)(n0 < N ? n0 : 0) * (size_t)ldb;
    size_t br1 = (size_t)(n1 < N ? n1 : 0) * (size_t)ldb;

    float acc[8][8];
#pragma unroll
    for (int i = 0; i < 8; i++)
#pragma unroll
        for (int j = 0; j < 8; j++) acc[i][j] = 0.0f;

    for (int kb = 0; kb < K; kb += 16) {
        float4 a0 = *(const float4*)(A  + ar0 + kb + lk);
        float4 a1 = *(const float4*)(A  + ar1 + kb + lk);
        float4 b0 = *(const float4*)(Bw + br0 + kb + lk);
        float4 b1 = *(const float4*)(Bw + br1 + kb + lk);
        __syncthreads();
        sA[lk+0][lr] = a0.x; sA[lk+1][lr] = a0.y; sA[lk+2][lr] = a0.z; sA[lk+3][lr] = a0.w;
        sA[lk+0][lr+64] = a1.x; sA[lk+1][lr+64] = a1.y; sA[lk+2][lr+64] = a1.z; sA[lk+3][lr+64] = a1.w;
        sB[lk+0][lr] = b0.x; sB[lk+1][lr] = b0.y; sB[lk+2][lr] = b0.z; sB[lk+3][lr] = b0.w;
        sB[lk+0][lr+64] = b1.x; sB[lk+1][lr+64] = b1.y; sB[lk+2][lr+64] = b1.z; sB[lk+3][lr+64] = b1.w;
        __syncthreads();
#pragma unroll
        for (int k = 0; k < 16; k++) {
            float4 pa0 = *(const float4*)(&sA[k][ty*8]);
            float4 pa1 = *(const float4*)(&sA[k][ty*8+4]);
            float4 pb0 = *(const float4*)(&sB[k][tx*8]);
            float4 pb1 = *(const float4*)(&sB[k][tx*8+4]);
            float av[8] = {pa0.x, pa0.y, pa0.z, pa0.w, pa1.x, pa1.y, pa1.z, pa1.w};
            float bv[8] = {pb0.x, pb0.y, pb0.z, pb0.w, pb1.x, pb1.y, pb1.z, pb1.w};
#pragma unroll
            for (int i = 0; i < 8; i++)
#pragma unroll
                for (int j = 0; j < 8; j++)
                    acc[i][j] += av[i] * bv[j];
        }
    }

#pragma unroll
    for (int i = 0; i < 8; i++) {
        int m = bm + ty*8 + i;
        if (m < M) {
            float* crow = C + (size_t)m * (size_t)N;
#pragma unroll
            for (int j = 0; j < 8; j++) {
                int n = bn + tx*8 + j;
                if (n < N) crow[n] = acc[i][j] + (bias ? bias[n] : 0.0f);
            }
        }
    }
}

// ---------------- persistent encoder: 32 blocks, resident weights, 1 barrier/step ----------------
// block owns 16 h-cols; smem weights = 48 gate rows x 512 (c = g*16 + l; src row = g*512 + nc0 + l)
__global__ void __launch_bounds__(TB2)
k_encoder(const float* __restrict__ bih, const float* __restrict__ bhh)
{
    extern __shared__ __align__(16) char dsm[];
    __nv_bfloat16* hbuf = (__nv_bfloat16*)dsm;            // 64 x 520
    __nv_bfloat16* wbuf = (__nv_bfloat16*)(dsm + 66560);  // 48 x 520
    float* sC = (float*)dsm;                              // alias (64 x 48)

    const int tid  = threadIdx.x;
    const int warp = tid >> 5;
    const int mi = warp & 3;        // m tile (16 rows)
    const int nj = warp >> 2;       // gate (0..2)
    const int nc0 = blockIdx.x * 16;

    for (int idx = tid; idx < 3072; idx += TB2) {
        int row = idx >> 6, q = idx & 63;
        int src = ((row >> 4) << 9) + nc0 + (row & 15);
        *(uint4*)(wbuf + row*520 + q*8) = *(const uint4*)(g_Whhbf + (size_t)src*HID + q*8);
    }
    unsigned gen = 0;
    if (tid == 0) gen = atomicAdd(&g_bargen, 0u);
    __syncthreads();

    for (int t = 0; t < LEN; t++) {
        for (int idx = tid; idx < 4096; idx += TB2) {
            int row = idx >> 6, q = idx & 63;
            *(uint4*)(hbuf + row*520 + q*8) = *(const uint4*)(g_hbf + row*HID + q*8);
        }
        __syncthreads();

        wmma::fragment<wmma::accumulator,16,16,16,float> fc;
        wmma::fill_fragment(fc, 0.0f);
#pragma unroll 4
        for (int k = 0; k < 512; k += 16) {
            wmma::fragment<wmma::matrix_a,16,16,16,__nv_bfloat16,wmma::row_major> fa;
            wmma::fragment<wmma::matrix_b,16,16,16,__nv_bfloat16,wmma::col_major> fb;
            wmma::load_matrix_sync(fa, hbuf + (mi*16)*520 + k, 520);
            wmma::load_matrix_sync(fb, wbuf + (nj*16)*520 + k, 520);
            wmma::mma_sync(fc, fa, fb, fc);
        }
        __syncthreads();
        wmma::store_matrix_sync(sC + (mi*16)*48 + nj*16, fc, 48, wmma::mem_row_major);
        __syncthreads();

        for (int idx = tid; idx < 1024; idx += TB2) {
            int b = idx >> 4, l = idx & 15;
            int j = nc0 + l;
            const float* gx = g_encGx + ((size_t)t*BSZ + b)*G3;
            float hr = sC[b*48 + l]      + bhh[j];
            float hz = sC[b*48 + 16 + l] + bhh[j+512];
            float hn = sC[b*48 + 32 + l] + bhh[j+1024];
            float r = sigmf(gx[j]      + bih[j]      + hr);
            float z = sigmf(gx[j+512]  + bih[j+512]  + hz);
            float n = tanhf(gx[j+1024] + bih[j+1024] + r * hn);
            float hp = g_h[b*HID + j];
            float h2 = (1.0f - z)*n + z*hp;
            g_h[b*HID + j] = h2;
            g_hbf[b*HID + j] = __float2bfloat16(h2);
            if (t == 0) g_enc0[b*HID + j] = h2;
        }
        gridbar32(gen);
    }
}

// ---------------- persistent decoder: 32 blocks, resident weights, 2 barriers/step ----------------
__global__ void __launch_bounds__(TB2)
k_decoder(const float* __restrict__ attn_W,
          const float* __restrict__ bih, const float* __restrict__ bhh)
{
    extern __shared__ __align__(16) char dsm[];
    __nv_bfloat16* iobuf = (__nv_bfloat16*)dsm;            // 64 x 520 (staged c, then h)
    __nv_bfloat16* wbuf  = (__nv_bfloat16*)(dsm + 66560);  // 96 x 520 (48 Wih + 48 Whh)
    float* sC  = (float*)dsm;                              // alias (64 x 96)
    float* sh  = (float*)dsm;                              // P1: 4 x 512
    float* slg = (float*)(dsm + 8192);                     // P1: 4 x 400
    float* srd = (float*)(dsm + 14592);                    // P1: 384
    float* sa0 = (float*)(dsm + 16128);                    // P1: 4

    const int tid  = threadIdx.x;
    const int warp = tid >> 5;
    const int mi = warp & 3;
    const int nj = warp >> 2;
    const int blk = blockIdx.x;
    const int nc0 = blk * 16;

    for (int idx = tid; idx < 6144; idx += TB2) {
        int row = idx >> 6, q = idx & 63;
        int c = (row < 48) ? row : row - 48;
        const __nv_bfloat16* W = (row < 48) ? g_dWihbf : g_dWhhbf;
        int src = ((c >> 4) << 9) + nc0 + (c & 15);
        *(uint4*)(wbuf + row*520 + q*8) = *(const uint4*)(W + (size_t)src*HID + q*8);
    }
    unsigned gen = 0;
    if (tid == 0) gen = atomicAdd(&g_bargen, 0u);
    __syncthreads();

    for (int t = 0; t < TOUT; t++) {
        // ---- P1: attention + cfuse (blocks 0..15, 4 batches each) ----
        if (blk < 16) {
            int b0 = blk * 4;
            for (int i = tid; i < 2048; i += TB2) sh[i] = g_h[b0*HID + i];
            __syncthreads();
            for (int id = tid; id < 1600; id += TB2) {
                int bi = id & 3, l = id >> 2;
                const float4* w4 = (const float4*)(attn_W + (size_t)l*1024 + 512);
                const float4* h4 = (const float4*)(sh + bi*512);
                float s = 0.0f;
#pragma unroll 4
                for (int k = 0; k < 128; k++) {
                    float4 w = w4[k], h = h4[k];
                    s += w.x*h.x + w.y*h.y + w.z*h.z + w.w*h.w;
                }
                slg[bi*400 + l] = g_attnx[((size_t)t*BSZ + (b0+bi))*LMAX + l] + s;
            }
            __syncthreads();
            {
                int bi = tid & 3, u = tid >> 2;
                float p = 0.0f;
                for (int l = u; l < 400; l += 96) p += expf(slg[bi*400 + l]);
                srd[tid] = p;
                __syncthreads();
                if (tid < 192) srd[tid] += srd[tid + 192];
                __syncthreads();
                if (tid < 96)  srd[tid] += srd[tid + 96];
                __syncthreads();
                if (tid < 48)  srd[tid] += srd[tid + 48];
                __syncthreads();
                if (tid < 24)  srd[tid] += srd[tid + 24];
                __syncthreads();
                if (tid < 12)  srd[tid] += srd[tid + 12];
                __syncthreads();
                if (tid < 4)   sa0[tid] = expf(slg[tid*400]) / (srd[tid] + srd[tid+4] + srd[tid+8]);
                __syncthreads();
            }
            for (int i = tid; i < 2048; i += TB2) {
                int bi = i >> 9, j = i & 511;
                int b = b0 + bi;
                float v = g_combx[((size_t)t*BSZ + b)*HID + j] + sa0[bi] * g_enc0W[b*HID + j];
                g_cbf[b*HID + j] = __float2bfloat16(v > 0.0f ? v : 0.0f);
            }
        }
        gridbar32(gen);

        // ---- P2: both GEMMs from resident weights + block-local fuse ----
        for (int idx = tid; idx < 4096; idx += TB2) {
            int row = idx >> 6, q = idx & 63;
            *(uint4*)(iobuf + row*520 + q*8) = *(const uint4*)(g_cbf + row*HID + q*8);
        }
        __syncthreads();

        wmma::fragment<wmma::accumulator,16,16,16,float> fc0, fc1;
        wmma::fill_fragment(fc0, 0.0f);
#pragma unroll 4
        for (int k = 0; k < 512; k += 16) {
            wmma::fragment<wmma::matrix_a,16,16,16,__nv_bfloat16,wmma::row_major> fa;
            wmma::fragment<wmma::matrix_b,16,16,16,__nv_bfloat16,wmma::col_major> fb;
            wmma::load_matrix_sync(fa, iobuf + (mi*16)*520 + k, 520);
            wmma::load_matrix_sync(fb, wbuf + (nj*16)*520 + k, 520);
            wmma::mma_sync(fc0, fa, fb, fc0);
        }
        __syncthreads();

        for (int idx = tid; idx < 4096; idx += TB2) {
            int row = idx >> 6, q = idx & 63;
            *(uint4*)(iobuf + row*520 + q*8) = *(const uint4*)(g_hbf + row*HID + q*8);
        }
        __syncthreads();

        wmma::fill_fragment(fc1, 0.0f);
#pragma unroll 4
        for (int k = 0; k < 512; k += 16) {
            wmma::fragment<wmma::matrix_a,16,16,16,__nv_bfloat16,wmma::row_major> fa;
            wmma::fragment<wmma::matrix_b,16,16,16,__nv_bfloat16,wmma::col_major> fb;
            wmma::load_matrix_sync(fa, iobuf + (mi*16)*520 + k, 520);
            wmma::load_matrix_sync(fb, wbuf + (48 + nj*16)*520 + k, 520);
            wmma::mma_sync(fc1, fa, fb, fc1);
        }
        __syncthreads();

        wmma::store_matrix_sync(sC + (mi*16)*96 + nj*16,      fc0, 96, wmma::mem_row_major);
        wmma::store_matrix_sync(sC + (mi*16)*96 + 48 + nj*16, fc1, 96, wmma::mem_row_major);
        __syncthreads();

        for (int idx = tid; idx < 1024; idx += TB2) {
            int b = idx >> 4, l = idx & 15;
            int j = nc0 + l;
            float ir  = sC[b*96 + l];
            float iz  = sC[b*96 + 16 + l];
            float inn = sC[b*96 + 32 + l];
            float hr  = sC[b*96 + 48 + l] + bhh[j];
            float hz  = sC[b*96 + 64 + l] + bhh[j+512];
            float hn  = sC[b*96 + 80 + l] + bhh[j+1024];
            float r = sigmf(ir + bih[j]      + hr);
            float z = sigmf(iz + bih[j+512]  + hz);
            float n = tanhf(inn + bih[j+1024] + r * hn);
            float hp = g_h[b*HID + j];
            float h2 = (1.0f - z)*n + z*hp;
            g_h[b*HID + j] = h2;
            g_hbf[b*HID + j] = __float2bfloat16(h2);
            g_H2bf[(size_t)t*BSZ*HID + b*HID + j] = __float2bfloat16(h2);
        }
        gridbar32(gen);
    }
}

// ---------------- final logsumexp combine + deterministic loss ----------------
__global__ void k_reduce()
{
    __shared__ float sred[256];
    int m = blockIdx.x * 256 + threadIdx.x;
    const float* pm = g_pm + (size_t)m * NCB;
    const float* ps = g_ps + (size_t)m * NCB;
    float M = pm[0];
    for (int j = 1; j < NCB; j++) M = fmaxf(M, pm[j]);
    float S = 0.0f;
    for (int j = 0; j < NCB; j++) S += ps[j] * expf(pm[j] - M);
    float contrib = (M + logf(S) - g_tgtlog[m]) * (1.0f / 64.0f);
    sred[threadIdx.x] = contrib;
    __syncthreads();
    for (int off = 128; off > 0; off >>= 1) {
        if (threadIdx.x < off) sred[threadIdx.x] += sred[threadIdx.x + off];
        __syncthreads();
    }
    if (threadIdx.x == 0) g_lossp[blockIdx.x] = sred[0];
}

__global__ void k_final(float* __restrict__ out)
{
    float s = 0.0f;
    for (int i = 0; i < 25; i++) s += g_lossp[i];
    out[0] = s;
}

// ---------------- host launcher ----------------
extern "C" void kernel_launch(void* const* d_in, const int* in_sizes, int n_in,
                              void* d_out, int out_size)
{
    const float* emb     = (const float*)d_in[0];
    const float* enc_Wih = (const float*)d_in[1];
    const float* enc_Whh = (const float*)d_in[2];
    const float* enc_bih = (const float*)d_in[3];
    const float* enc_bhh = (const float*)d_in[4];
    const float* attn_W  = (const float*)d_in[5];
    const float* attn_b  = (const float*)d_in[6];
    const float* comb_W  = (const float*)d_in[7];
    const float* comb_b  = (const float*)d_in[8];
    const float* dec_Wih = (const float*)d_in[9];
    const float* dec_Whh = (const float*)d_in[10];
    const float* dec_bih = (const float*)d_in[11];
    const float* dec_bhh = (const float*)d_in[12];
    const float* out_W   = (const float*)d_in[13];
    const float* out_b   = (const float*)d_in[14];
    const int*   in_tok  = (const int*)d_in[15];
    const int*   tgt     = (const int*)d_in[16];

    float *p_attnx, *p_combx, *p_enc0, *p_enc0W, *p_encGx;
    int *p_dectok;
    __nv_bfloat16 *p_embbf, *p_Wobf, *p_Wihbf, *p_Whhbf, *p_dWihbf, *p_dWhhbf, *p_H2bf;
    cudaGetSymbolAddress((void**)&p_encGx, g_encGx);
    cudaGetSymbolAddress((void**)&p_attnx, g_attnx);
    cudaGetSymbolAddress((void**)&p_combx, g_combx);
    cudaGetSymbolAddress((void**)&p_enc0,  g_enc0);
    cudaGetSymbolAddress((void**)&p_enc0W, g_enc0W);
    cudaGetSymbolAddress((void**)&p_dectok, g_dectok);
    cudaGetSymbolAddress((void**)&p_embbf, g_embbf);
    cudaGetSymbolAddress((void**)&p_Wobf,  g_Wobf);
    cudaGetSymbolAddress((void**)&p_Wihbf, g_Wihbf);
    cudaGetSymbolAddress((void**)&p_Whhbf, g_Whhbf);
    cudaGetSymbolAddress((void**)&p_dWihbf, g_dWihbf);
    cudaGetSymbolAddress((void**)&p_dWhhbf, g_dWhhbf);
    cudaGetSymbolAddress((void**)&p_H2bf,  g_H2bf);

    cudaFuncSetAttribute(k_encoder, cudaFuncAttributeMaxDynamicSharedMemorySize, 116480);
    cudaFuncSetAttribute(k_decoder, cudaFuncAttributeMaxDynamicSharedMemorySize, 166400);

    k_init<<<128, 256>>>(tgt);
    k_tobf<<<(VOC*HID)/1024, 256>>>(emb,     p_embbf, VOC*HID);
    k_tobf<<<(VOC*HID)/1024, 256>>>(out_W,   p_Wobf,  VOC*HID);
    k_tobf<<<(G3*HID)/1024,  256>>>(enc_Wih, p_Wihbf, G3*HID);
    k_tobf<<<(G3*HID)/1024,  256>>>(enc_Whh, p_Whhbf, G3*HID);
    k_tobf<<<(G3*HID)/1024,  256>>>(dec_Wih, p_dWihbf, G3*HID);
    k_tobf<<<(G3*HID)/1024,  256>>>(dec_Whh, p_dWhhbf, G3*HID);

    // phase A
    k_wgemm<0><<<dim3(12, 200), 256>>>(p_embbf, in_tok, p_Wihbf,
                                       (const float*)0, p_encGx, G3,
                                       (const int*)0, G3);
    k_sgemm128<true><<<dim3(4, 50), 256>>>(emb, p_dectok, attn_W, 1024, attn_b, p_attnx, MROWS, LMAX, HID);
    k_sgemm128<true><<<dim3(4, 50), 256>>>(emb, p_dectok, comb_W, 1024, comb_b, p_combx, MROWS, HID, HID);

    // phase B1: persistent encoder (resident weights)
    k_encoder<<<NB2, TB2, 116480>>>(enc_bih, enc_bhh);

    // enc0W = enc0 @ comb_W[:, H:]^T
    k_sgemm128<false><<<dim3(4, 1), 256>>>(p_enc0, (const int*)0, comb_W + 512, 1024,
                                           (const float*)0, p_enc0W, BSZ, HID, HID);

    // phase B2: persistent decoder (resident weights)
    k_decoder<<<NB2, TB2, 166400>>>(attn_W, dec_bih, dec_bhh);

    // phase C: projection + fused logsumexp partials
    k_wgemm<1><<<dim3(NCB, 50), 256>>>(p_H2bf, (const int*)0, p_Wobf, out_b,
                                       (float*)0, 0, tgt, VOC);
    k_reduce<<<25, 256>>>();
    k_final<<<1, 1>>>((float*)d_out);
}

// round 14
// speedup vs baseline: 2.3194x; 2.3194x over previous
#include <cuda_runtime.h>
#include <cuda_bf16.h>
#include <mma.h>
#include <math.h>

using namespace nvcuda;

// ---------------- problem constants ----------------
#define BSZ   64
#define HID   512
#define G3    1536
#define LEN   400
#define TOUT  100
#define VOC   50000
#define LMAX  400
#define MROWS (TOUT*BSZ)
#define NCB   391           // phase-C column blocks: ceil(50000/128)
#define NBLK  148
#define KDIM  512

// ---------------- device scratch ----------------
__device__ float g_encGx[(size_t)LEN*BSZ*G3];
__device__ float g_attnx[(size_t)TOUT*BSZ*LMAX];
__device__ float g_combx[(size_t)TOUT*BSZ*HID];
__device__ int   g_dectok[TOUT*BSZ];
__device__ float g_h[BSZ*HID];
__device__ __nv_bfloat16 g_hbf[BSZ*HID];
__device__ __nv_bfloat16 g_cbf[BSZ*HID];
__device__ float g_enc0[BSZ*HID];
__device__ float g_enc0W[BSZ*HID];
__device__ float g_part[4*BSZ*G3];
__device__ __nv_bfloat16 g_H2bf[(size_t)MROWS*HID];
__device__ __nv_bfloat16 g_embbf[(size_t)VOC*HID];
__device__ __nv_bfloat16 g_Wobf[(size_t)VOC*HID];
__device__ __nv_bfloat16 g_Wihbf[(size_t)G3*HID];
__device__ __nv_bfloat16 g_Whhbf[(size_t)G3*HID];
__device__ __nv_bfloat16 g_dWihbf[(size_t)G3*HID];
__device__ __nv_bfloat16 g_dWhhbf[(size_t)G3*HID];
__device__ float g_pm[(size_t)MROWS*NCB];
__device__ float g_ps[(size_t)MROWS*NCB];
__device__ float g_tgtlog[MROWS];
__device__ float g_lossp[32];

// distributed-flag grid barrier state (zero-initialized; monotone generations persist across replays)
__device__ unsigned g_arr[NBLK];
__device__ unsigned g_rel;

__device__ __forceinline__ float sigmf(float x) { return 1.0f / (1.0f + expf(-x)); }

// arrival: per-block flag store (no RMW). block 0 scans flags with 148 parallel threads,
// publishes release word. waiters poll release with plain volatile loads.
__device__ __forceinline__ void gridbar(unsigned &gen)
{
    __syncthreads();
    const int tid = threadIdx.x;
    if (blockIdx.x == 0) {
        if (tid > 0 && tid < NBLK) {
            volatile unsigned* a = g_arr + tid;
            while (*a < gen + 1u) { }
        }
        __syncthreads();
        if (tid == 0) {
            __threadfence();
            *(volatile unsigned*)&g_rel = gen + 1u;
        }
    } else {
        if (tid == 0) {
            __threadfence();
            *(volatile unsigned*)&g_arr[blockIdx.x] = gen + 1u;
            volatile unsigned* r = &g_rel;
            while (*r < gen + 1u) { }
        }
    }
    gen++;
    __syncthreads();
}

// ---------------- one-shot fp32 -> bf16 conversion of all six arrays ----------------
__global__ void k_tobfAll(const float* __restrict__ emb, const float* __restrict__ outW,
                          const float* __restrict__ w0, const float* __restrict__ w1,
                          const float* __restrict__ w2, const float* __restrict__ w3)
{
    int bid = blockIdx.x;
    const float* s;
    __nv_bfloat16* d;
    int base;
    if (bid < 25000) { s = emb; d = g_embbf; base = bid; }
    else if (bid < 50000) { s = outW; d = g_Wobf; base = bid - 25000; }
    else {
        int r = bid - 50000;
        int arr = r / 768;
        base = r % 768;
        s = (arr == 0) ? w0 : (arr == 1) ? w1 : (arr == 2) ? w2 : w3;
        d = (arr == 0) ? g_Wihbf : (arr == 1) ? g_Whhbf : (arr == 2) ? g_dWihbf : g_dWhhbf;
    }
    int i = (base * 256 + threadIdx.x) << 2;
    float4 v = *(const float4*)(s + i);
    *(__nv_bfloat162*)(d + i)     = __floats2bfloat162_rn(v.x, v.y);
    *(__nv_bfloat162*)(d + i + 2) = __floats2bfloat162_rn(v.z, v.w);
}

__global__ void k_init(const int* __restrict__ tgt)
{
    int i = blockIdx.x * 256 + threadIdx.x;
    if (i < BSZ*HID) {
        g_h[i] = 0.0f;
        g_hbf[i] = __float2bfloat16(0.0f);
    }
    if (i < TOUT*BSZ) {
        int t = i / BSZ, b = i % BSZ;
        g_dectok[i] = (t == 0) ? 1 : tgt[(t-1)*BSZ + b];
    }
}

// ================= bf16 WMMA GEMM, 128x128 block, K=512, double-buffered =================
template<int MODE>
__global__ void __launch_bounds__(256)
k_wgemm(const __nv_bfloat16* __restrict__ Abf,
        const int* __restrict__ gidx,
        const __nv_bfloat16* __restrict__ Bbf,
        const float* __restrict__ bias,
        float* __restrict__ Cout, int ldC,
        const int* __restrict__ tgt,
        int Ncols)
{
    __shared__ __align__(16) char sbuf[40960];
    float* sC = (float*)sbuf;

    const int tid  = threadIdx.x;
    const int warp = tid >> 5;
    const int rt = warp & 3;
    const int cn = warp >> 2;
    const int bm = blockIdx.y * 128;
    const int bn = blockIdx.x * 128;

    const int cr = tid >> 2;
    const int q8 = (tid & 3) << 3;

    size_t ga0, ga1;
    if (MODE == 0) {
        ga0 = (size_t)gidx[bm + cr]      * KDIM + q8;
        ga1 = (size_t)gidx[bm + cr + 64] * KDIM + q8;
    } else {
        ga0 = (size_t)(bm + cr)      * KDIM + q8;
        ga1 = (size_t)(bm + cr + 64) * KDIM + q8;
    }
    int nb0 = bn + cr;      if (nb0 >= Ncols) nb0 = Ncols - 1;
    int nb1 = bn + cr + 64; if (nb1 >= Ncols) nb1 = Ncols - 1;
    size_t gb0 = (size_t)nb0 * KDIM + q8;
    size_t gb1 = (size_t)nb1 * KDIM + q8;

    const int sa0 = cr*40 + q8;
    const int sa1 = sa0 + 64*40;

    __nv_bfloat16* bufA[2] = { (__nv_bfloat16*)sbuf, (__nv_bfloat16*)(sbuf + 20480) };
    __nv_bfloat16* bufB[2] = { (__nv_bfloat16*)(sbuf + 10240), (__nv_bfloat16*)(sbuf + 30720) };

    uint4 rA0 = *(const uint4*)(Abf + ga0);
    uint4 rA1 = *(const uint4*)(Abf + ga1);
    uint4 rB0 = *(const uint4*)(Bbf + gb0);
    uint4 rB1 = *(const uint4*)(Bbf + gb1);
    *(uint4*)(bufA[0] + sa0) = rA0;
    *(uint4*)(bufA[0] + sa1) = rA1;
    *(uint4*)(bufB[0] + sa0) = rB0;
    *(uint4*)(bufB[0] + sa1) = rB1;
    __syncthreads();

    wmma::fragment<wmma::accumulator, 16, 16, 16, float> fc[2][4];
    for (int mi = 0; mi < 2; mi++)
        for (int ni = 0; ni < 4; ni++)
            wmma::fill_fragment(fc[mi][ni], 0.0f);

    for (int it = 0; it < 16; it++) {
        if (it < 15) {
            int kg = (it + 1) * 32;
            rA0 = *(const uint4*)(Abf + ga0 + kg);
            rA1 = *(const uint4*)(Abf + ga1 + kg);
            rB0 = *(const uint4*)(Bbf + gb0 + kg);
            rB1 = *(const uint4*)(Bbf + gb1 + kg);
        }
        __nv_bfloat16* cA = bufA[it & 1];
        __nv_bfloat16* cB = bufB[it & 1];
        for (int kk = 0; kk < 32; kk += 16) {
            wmma::fragment<wmma::matrix_a, 16, 16, 16, __nv_bfloat16, wmma::row_major> fa[2];
            wmma::fragment<wmma::matrix_b, 16, 16, 16, __nv_bfloat16, wmma::col_major> fb[4];
            wmma::load_matrix_sync(fa[0], cA + (rt*32     )*40 + kk, 40);
            wmma::load_matrix_sync(fa[1], cA + (rt*32 + 16)*40 + kk, 40);
            for (int ni = 0; ni < 4; ni++)
                wmma::load_matrix_sync(fb[ni], cB + (cn*64 + ni*16)*40 + kk, 40);
            for (int mi = 0; mi < 2; mi++)
                for (int ni = 0; ni < 4; ni++)
                    wmma::mma_sync(fc[mi][ni], fa[mi], fb[ni], fc[mi][ni]);
        }
        if (it < 15) {
            __nv_bfloat16* nA = bufA[(it + 1) & 1];
            __nv_bfloat16* nB = bufB[(it + 1) & 1];
            *(uint4*)(nA + sa0) = rA0;
            *(uint4*)(nA + sa1) = rA1;
            *(uint4*)(nB + sa0) = rB0;
            *(uint4*)(nB + sa1) = rB1;
        }
        __syncthreads();
    }

    if (MODE == 0) {
        for (int mi = 0; mi < 2; mi++)
            for (int ni = 0; ni < 4; ni++) {
                size_t row = bm + rt*32 + mi*16;
                int col = bn + cn*64 + ni*16;
                wmma::store_matrix_sync(Cout + row * (size_t)ldC + col,
                                        fc[mi][ni], ldC, wmma::mem_row_major);
            }
    } else {
        const int r  = tid >> 1;
        const int hf = tid & 1;
        const int rg = bm + r;
        const int tv = tgt[rg];
        float Mrun = -1e30f, Srun = 0.0f;

        for (int h = 0; h < 2; h++) {
            if (cn == h) {
                for (int mi = 0; mi < 2; mi++)
                    for (int ni = 0; ni < 4; ni++)
                        wmma::store_matrix_sync(sC + (rt*32 + mi*16)*72 + ni*16,
                                                fc[mi][ni], 72, wmma::mem_row_major);
            }
            __syncthreads();

            float* crow = sC + r*72 + hf*32;
            int cbase = bn + h*64 + hf*32;
            float mx = -1e30f;
            for (int c = 0; c < 32; c++) {
                int gc = cbase + c;
                float v = (gc < Ncols) ? (crow[c] + bias[gc]) : -1e30f;
                crow[c] = v;
                mx = fmaxf(mx, v);
            }
            float s = 0.0f;
            for (int c = 0; c < 32; c++) s += expf(crow[c] - mx);

            float mo = __shfl_xor_sync(0xffffffffu, mx, 1);
            float so = __shfl_xor_sync(0xffffffffu, s,  1);
            float M2 = fmaxf(mx, mo);
            float S2 = s * expf(mx - M2) + so * expf(mo - M2);

            int lc = tv - cbase;
            if (lc >= 0 && lc < 32) g_tgtlog[rg] = crow[lc];

            float nm = fmaxf(Mrun, M2);
            Srun = Srun * expf(Mrun - nm) + S2 * expf(M2 - nm);
            Mrun = nm;
            __syncthreads();
        }
        if (hf == 0) {
            g_pm[(size_t)rg * NCB + blockIdx.x] = Mrun;
            g_ps[(size_t)rg * NCB + blockIdx.x] = Srun;
        }
    }
}

// ---------------- generic fp32 SGEMM (small phase-A ops) ----------------
template<bool GATHER>
__global__ void __launch_bounds__(256)
k_sgemm128(const float* __restrict__ A,
           const int*  __restrict__ gidx,
           const float* __restrict__ Bw, int ldb,
           const float* __restrict__ bias,
           float* __restrict__ C,
           int M, int N, int K)
{
    __shared__ __align__(16) float sA[16][128];
    __shared__ __align__(16) float sB[16][128];
    const int tid = threadIdx.x;
    const int bm = blockIdx.y * 128;
    const int bn = blockIdx.x * 128;
    const int tx = tid & 15;
    const int ty = tid >> 4;
    const int lr = tid >> 2;
    const int lk = (tid & 3) << 2;

    int m0 = bm + lr, m1 = m0 + 64;
    const bool mv0 = m0 < M, mv1 = m1 < M;
    size_t ar0, ar1;
    if (GATHER) {
        ar0 = (size_t)(mv0 ? gidx[m0] : gidx[0]) * (size_t)K;
        ar1 = (size_t)(mv1 ? gidx[m1] : gidx[0]) * (size_t)K;
    } else {
        ar0 = (size_t)(mv0 ? m0 : 0) * (size_t)K;
        ar1 = (size_t)(mv1 ? m1 : 0) * (size_t)K;
    }
    int n0 = bn + lr, n1 = n0 + 64;
    size_t br0 = (size_t)(n0 < N ? n0 : 0) * (size_t)ldb;
    size_t br1 = (size_t)(n1 < N ? n1 : 0) * (size_t)ldb;

    float acc[8][8];
#pragma unroll
    for (int i = 0; i < 8; i++)
#pragma unroll
        for (int j = 0; j < 8; j++) acc[i][j] = 0.0f;

    for (int kb = 0; kb < K; kb += 16) {
        float4 a0 = *(const float4*)(A  + ar0 + kb + lk);
        float4 a1 = *(const float4*)(A  + ar1 + kb + lk);
        float4 b0 = *(const float4*)(Bw + br0 + kb + lk);
        float4 b1 = *(const float4*)(Bw + br1 + kb + lk);
        __syncthreads();
        sA[lk+0][lr] = a0.x; sA[lk+1][lr] = a0.y; sA[lk+2][lr] = a0.z; sA[lk+3][lr] = a0.w;
        sA[lk+0][lr+64] = a1.x; sA[lk+1][lr+64] = a1.y; sA[lk+2][lr+64] = a1.z; sA[lk+3][lr+64] = a1.w;
        sB[lk+0][lr] = b0.x; sB[lk+1][lr] = b0.y; sB[lk+2][lr] = b0.z; sB[lk+3][lr] = b0.w;
        sB[lk+0][lr+64] = b1.x; sB[lk+1][lr+64] = b1.y; sB[lk+2][lr+64] = b1.z; sB[lk+3][lr+64] = b1.w;
        __syncthreads();
#pragma unroll
        for (int k = 0; k < 16; k++) {
            float4 pa0 = *(const float4*)(&sA[k][ty*8]);
            float4 pa1 = *(const float4*)(&sA[k][ty*8+4]);
            float4 pb0 = *(const float4*)(&sB[k][tx*8]);
            float4 pb1 = *(const float4*)(&sB[k][tx*8+4]);
            float av[8] = {pa0.x, pa0.y, pa0.z, pa0.w, pa1.x, pa1.y, pa1.z, pa1.w};
            float bv[8] = {pb0.x, pb0.y, pb0.z, pb0.w, pb1.x, pb1.y, pb1.z, pb1.w};
#pragma unroll
            for (int i = 0; i < 8; i++)
#pragma unroll
                for (int j = 0; j < 8; j++)
                    acc[i][j] += av[i] * bv[j];
        }
    }

#pragma unroll
    for (int i = 0; i < 8; i++) {
        int m = bm + ty*8 + i;
        if (m < M) {
            float* crow = C + (size_t)m * (size_t)N;
#pragma unroll
            for (int j = 0; j < 8; j++) {
                int n = bn + tx*8 + j;
                if (n < N) crow[n] = acc[i][j] + (bias ? bias[n] : 0.0f);
            }
        }
    }
}

// ---------------- per-task 64x64 WMMA step-GEMM, K=256, double-buffered ----------------
__device__ __forceinline__ void step_wmma_task(
    const __nv_bfloat16* __restrict__ A, const __nv_bfloat16* __restrict__ B,
    int bn, int kbase, float* __restrict__ Cp, char* sbuf)
{
    const int tid  = threadIdx.x;
    const int warp = tid >> 5;
    const int wm = warp >> 2;
    const int wn = warp & 3;
    const int cr = tid >> 2;
    const int q8 = (tid & 3) << 3;

    size_t aoff = (size_t)cr * HID + kbase + q8;
    size_t boff = (size_t)(bn + cr) * HID + kbase + q8;
    const int si = cr*40 + q8;

    __nv_bfloat16* bufA[2] = { (__nv_bfloat16*)sbuf, (__nv_bfloat16*)(sbuf + 10240) };
    __nv_bfloat16* bufB[2] = { (__nv_bfloat16*)(sbuf + 5120), (__nv_bfloat16*)(sbuf + 15360) };

    uint4 ra = *(const uint4*)(A + aoff);
    uint4 rb = *(const uint4*)(B + boff);
    *(uint4*)(bufA[0] + si) = ra;
    *(uint4*)(bufB[0] + si) = rb;
    __syncthreads();

    wmma::fragment<wmma::accumulator,16,16,16,float> fc0, fc1;
    wmma::fill_fragment(fc0, 0.0f);
    wmma::fill_fragment(fc1, 0.0f);

    for (int it = 0; it < 8; it++) {
        if (it < 7) {
            int kg = (it + 1) * 32;
            ra = *(const uint4*)(A + aoff + kg);
            rb = *(const uint4*)(B + boff + kg);
        }
        __nv_bfloat16* cA = bufA[it & 1];
        __nv_bfloat16* cB = bufB[it & 1];
        for (int kk = 0; kk < 32; kk += 16) {
            wmma::fragment<wmma::matrix_a,16,16,16,__nv_bfloat16,wmma::row_major> fa0, fa1;
            wmma::fragment<wmma::matrix_b,16,16,16,__nv_bfloat16,wmma::col_major> fb;
            wmma::load_matrix_sync(fa0, cA + (wm*32     )*40 + kk, 40);
            wmma::load_matrix_sync(fa1, cA + (wm*32 + 16)*40 + kk, 40);
            wmma::load_matrix_sync(fb,  cB + (wn*16     )*40 + kk, 40);
            wmma::mma_sync(fc0, fa0, fb, fc0);
            wmma::mma_sync(fc1, fa1, fb, fc1);
        }
        if (it < 7) {
            __nv_bfloat16* nA = bufA[(it + 1) & 1];
            __nv_bfloat16* nB = bufB[(it + 1) & 1];
            *(uint4*)(nA + si) = ra;
            *(uint4*)(nB + si) = rb;
        }
        __syncthreads();
    }
    wmma::store_matrix_sync(Cp + (size_t)(wm*32     )*G3 + bn + wn*16, fc0, G3, wmma::mem_row_major);
    wmma::store_matrix_sync(Cp + (size_t)(wm*32 + 16)*G3 + bn + wn*16, fc1, G3, wmma::mem_row_major);
}

// ---------------- persistent encoder (148 blocks, 2 barriers/step) ----------------
__global__ void __launch_bounds__(256)
k_encoder(const float* __restrict__ bih, const float* __restrict__ bhh)
{
    __shared__ __align__(16) char sbuf[20480];
    unsigned gen = *(volatile unsigned*)&g_rel;
    const int blk = blockIdx.x;

    for (int t = 0; t < LEN; t++) {
        if (blk < 48) {
            int ks = blk / 24, nb = blk % 24;
            step_wmma_task(g_hbf, g_Whhbf, nb*64, ks*256, g_part + (size_t)ks*BSZ*G3, sbuf);
        }
        gridbar(gen);
        if (blk < 128) {
            int idx = blk*256 + threadIdx.x;
            int b = idx >> 9, j = idx & 511;
            int base = b * G3;
            float hr = bhh[j], hz = bhh[j+512], hn = bhh[j+1024];
#pragma unroll
            for (int s = 0; s < 2; s++) {
                const float* p = g_part + (size_t)s * BSZ * G3 + base;
                hr += p[j]; hz += p[j+512]; hn += p[j+1024];
            }
            const float* gx = g_encGx + ((size_t)t*BSZ + b) * G3;
            float r = sigmf(gx[j] + bih[j] + hr);
            float z = sigmf(gx[j+512] + bih[j+512] + hz);
            float n = tanhf(gx[j+1024] + bih[j+1024] + r * hn);
            float hp = g_h[idx];
            float h2 = (1.0f - z) * n + z * hp;
            g_h[idx] = h2;
            g_hbf[idx] = __float2bfloat16(h2);
            if (t == 0) g_enc0[idx] = h2;
        }
        gridbar(gen);
    }
}

// ---------------- persistent decoder (148 blocks, 3 barriers/step) ----------------
__global__ void __launch_bounds__(256)
k_decoder(const float* __restrict__ attn_W,
          const float* __restrict__ bih, const float* __restrict__ bhh)
{
    __shared__ __align__(16) char sbuf[20480];
    float* sm = (float*)sbuf;
    unsigned gen = *(volatile unsigned*)&g_rel;
    const int blk = blockIdx.x;
    const int tid = threadIdx.x;

    for (int t = 0; t < TOUT; t++) {
        // ---- P1: attention + cfuse for this block's batch (blocks 0..63) ----
        if (blk < 64) {
            const int b = blk;
            float* sh = sm;             // 512
            float* slg = sm + 512;      // 400
            float* sred = sm + 912;     // 256
            float* sa0 = sm + 1168;     // 1
            sh[tid]       = g_h[b*HID + tid];
            sh[tid + 256] = g_h[b*HID + tid + 256];
            __syncthreads();
            const float4* h4 = (const float4*)sh;
            for (int l = tid; l < LMAX; l += 256) {
                const float4* w4 = (const float4*)(attn_W + (size_t)l*1024 + 512);
                float s = 0.0f;
#pragma unroll 4
                for (int k = 0; k < 128; k++) {
                    float4 w = w4[k], h = h4[k];
                    s += w.x*h.x + w.y*h.y + w.z*h.z + w.w*h.w;
                }
                slg[l] = g_attnx[((size_t)t*BSZ + b)*LMAX + l] + s;
            }
            __syncthreads();
            float lm = -1e30f;
            for (int l = tid; l < LMAX; l += 256) lm = fmaxf(lm, slg[l]);
            sred[tid] = lm; __syncthreads();
            for (int off = 128; off > 0; off >>= 1) {
                if (tid < off) sred[tid] = fmaxf(sred[tid], sred[tid+off]);
                __syncthreads();
            }
            float mx = sred[0];
            __syncthreads();
            float ls = 0.0f;
            for (int l = tid; l < LMAX; l += 256) ls += expf(slg[l] - mx);
            sred[tid] = ls; __syncthreads();
            for (int off = 128; off > 0; off >>= 1) {
                if (tid < off) sred[tid] += sred[tid+off];
                __syncthreads();
            }
            if (tid == 0) sa0[0] = expf(slg[0] - mx) / sred[0];
            __syncthreads();
            float a0 = sa0[0];
            // cfuse for this batch (512 elems over 256 threads)
            for (int j = tid; j < HID; j += 256) {
                float v = g_combx[((size_t)t*BSZ + b)*HID + j] + a0 * g_enc0W[b*HID + j];
                g_cbf[b*HID + j] = __float2bfloat16(v > 0.0f ? v : 0.0f);
            }
        }
        gridbar(gen);
        // ---- P2: gate GEMMs ----
        if (blk < 96) {
            int group = blk / 48, rem = blk % 48;
            int ks = rem / 24, nb = rem % 24;
            const __nv_bfloat16* A  = group ? g_hbf : g_cbf;
            const __nv_bfloat16* Bm = group ? g_dWhhbf : g_dWihbf;
            step_wmma_task(A, Bm, nb*64, ks*256,
                           g_part + (size_t)(group*2 + ks)*BSZ*G3, sbuf);
        }
        gridbar(gen);
        // ---- P3: gate fuse ----
        if (blk < 128) {
            int idx = blk*256 + tid;
            int b = idx >> 9, j = idx & 511;
            int base = b * G3;
            float ir = bih[j], iz = bih[j+512], in = bih[j+1024];
            float hr = bhh[j], hz = bhh[j+512], hn = bhh[j+1024];
#pragma unroll
            for (int s = 0; s < 2; s++) {
                const float* pi = g_part + (size_t)s * BSZ * G3 + base;
                const float* ph = g_part + (size_t)(s+2) * BSZ * G3 + base;
                ir += pi[j]; iz += pi[j+512]; in += pi[j+1024];
                hr += ph[j]; hz += ph[j+512]; hn += ph[j+1024];
            }
            float r = sigmf(ir + hr);
            float z = sigmf(iz + hz);
            float n = tanhf(in + r * hn);
            float hp = g_h[idx];
            float h2 = (1.0f - z) * n + z * hp;
            g_h[idx] = h2;
            g_hbf[idx] = __float2bfloat16(h2);
            g_H2bf[(size_t)t*BSZ*HID + idx] = __float2bfloat16(h2);
        }
        gridbar(gen);
    }
}

// ---------------- final logsumexp combine + deterministic loss ----------------
__global__ void k_reduce()
{
    __shared__ float sred[256];
    int m = blockIdx.x * 256 + threadIdx.x;
    const float* pm = g_pm + (size_t)m * NCB;
    const float* ps = g_ps + (size_t)m * NCB;
    float M = pm[0];
    for (int j = 1; j < NCB; j++) M = fmaxf(M, pm[j]);
    float S = 0.0f;
    for (int j = 0; j < NCB; j++) S += ps[j] * expf(pm[j] - M);
    float contrib = (M + logf(S) - g_tgtlog[m]) * (1.0f / 64.0f);
    sred[threadIdx.x] = contrib;
    __syncthreads();
    for (int off = 128; off > 0; off >>= 1) {
        if (threadIdx.x < off) sred[threadIdx.x] += sred[threadIdx.x + off];
        __syncthreads();
    }
    if (threadIdx.x == 0) g_lossp[blockIdx.x] = sred[0];
}

__global__ void k_final(float* __restrict__ out)
{
    float s = 0.0f;
    for (int i = 0; i < 25; i++) s += g_lossp[i];
    out[0] = s;
}

// ---------------- host launcher ----------------
extern "C" void kernel_launch(void* const* d_in, const int* in_sizes, int n_in,
                              void* d_out, int out_size)
{
    const float* emb     = (const float*)d_in[0];
    const float* enc_Wih = (const float*)d_in[1];
    const float* enc_Whh = (const float*)d_in[2];
    const float* enc_bih = (const float*)d_in[3];
    const float* enc_bhh = (const float*)d_in[4];
    const float* attn_W  = (const float*)d_in[5];
    const float* attn_b  = (const float*)d_in[6];
    const float* comb_W  = (const float*)d_in[7];
    const float* comb_b  = (const float*)d_in[8];
    const float* dec_Wih = (const float*)d_in[9];
    const float* dec_Whh = (const float*)d_in[10];
    const float* dec_bih = (const float*)d_in[11];
    const float* dec_bhh = (const float*)d_in[12];
    const float* out_W   = (const float*)d_in[13];
    const float* out_b   = (const float*)d_in[14];
    const int*   in_tok  = (const int*)d_in[15];
    const int*   tgt     = (const int*)d_in[16];

    float *p_attnx, *p_combx, *p_enc0, *p_enc0W, *p_encGx;
    int *p_dectok;
    __nv_bfloat16 *p_embbf, *p_Wobf, *p_Wihbf, *p_H2bf;
    cudaGetSymbolAddress((void**)&p_encGx, g_encGx);
    cudaGetSymbolAddress((void**)&p_attnx, g_attnx);
    cudaGetSymbolAddress((void**)&p_combx, g_combx);
    cudaGetSymbolAddress((void**)&p_enc0,  g_enc0);
    cudaGetSymbolAddress((void**)&p_enc0W, g_enc0W);
    cudaGetSymbolAddress((void**)&p_dectok, g_dectok);
    cudaGetSymbolAddress((void**)&p_embbf, g_embbf);
    cudaGetSymbolAddress((void**)&p_Wobf,  g_Wobf);
    cudaGetSymbolAddress((void**)&p_Wihbf, g_Wihbf);
    cudaGetSymbolAddress((void**)&p_H2bf,  g_H2bf);

    // launch order arranged so k_encoder is launch index 5 (ncu -s 5 -c 1 captures it)
    k_init<<<128, 256>>>(tgt);                                                   // 0
    k_tobfAll<<<53072, 256>>>(emb, out_W, enc_Wih, enc_Whh, dec_Wih, dec_Whh);   // 1
    k_sgemm128<true><<<dim3(4, 50), 256>>>(emb, p_dectok, attn_W, 1024, attn_b,  // 2
                                           p_attnx, MROWS, LMAX, HID);
    k_sgemm128<true><<<dim3(4, 50), 256>>>(emb, p_dectok, comb_W, 1024, comb_b,  // 3
                                           p_combx, MROWS, HID, HID);
    k_wgemm<0><<<dim3(12, 200), 256>>>(p_embbf, in_tok, p_Wihbf,                 // 4
                                       (const float*)0, p_encGx, G3,
                                       (const int*)0, G3);
    k_encoder<<<NBLK, 256>>>(enc_bih, enc_bhh);                                  // 5 <- profiled

    k_sgemm128<false><<<dim3(4, 1), 256>>>(p_enc0, (const int*)0, comb_W + 512, 1024,
                                           (const float*)0, p_enc0W, BSZ, HID, HID);
    k_decoder<<<NBLK, 256>>>(attn_W, dec_bih, dec_bhh);
    k_wgemm<1><<<dim3(NCB, 50), 256>>>(p_H2bf, (const int*)0, p_Wobf, out_b,
                                       (float*)0, 0, tgt, VOC);
    k_reduce<<<25, 256>>>();
    k_final<<<1, 1>>>((float*)d_out);
}

// round 15
// speedup vs baseline: 2.5740x; 1.1098x over previous
#include <cuda_runtime.h>
#include <cuda_bf16.h>
#include <mma.h>
#include <math.h>

using namespace nvcuda;

// ---------------- problem constants ----------------
#define BSZ   64
#define HID   512
#define G3    1536
#define LEN   400
#define TOUT  100
#define VOC   50000
#define LMAX  400
#define MROWS (TOUT*BSZ)
#define NCB   391           // phase-C column blocks: ceil(50000/128)
#define NBLK  148
#define KDIM  512

// ---------------- device scratch ----------------
__device__ float g_encGx[(size_t)LEN*BSZ*G3];
__device__ float g_attnx[(size_t)TOUT*BSZ*512];   // padded stride 512 (cols 400..511 junk)
__device__ float g_combx[(size_t)TOUT*BSZ*HID];
__device__ int   g_dectok[TOUT*BSZ];
__device__ float g_h[BSZ*HID];
__device__ __nv_bfloat16 g_hbf[BSZ*HID];
__device__ __nv_bfloat16 g_cbf[BSZ*HID];
__device__ float g_enc0[BSZ*HID];
__device__ float g_enc0W[BSZ*HID];
__device__ float g_part[4*BSZ*G3];
__device__ __nv_bfloat16 g_H2bf[(size_t)MROWS*HID];
__device__ __nv_bfloat16 g_embbf[(size_t)VOC*HID];
__device__ __nv_bfloat16 g_Wobf[(size_t)VOC*HID];
__device__ __nv_bfloat16 g_Wihbf[(size_t)G3*HID];
__device__ __nv_bfloat16 g_Whhbf[(size_t)G3*HID];
__device__ __nv_bfloat16 g_dWihbf[(size_t)G3*HID];
__device__ __nv_bfloat16 g_dWhhbf[(size_t)G3*HID];
__device__ __nv_bfloat16 g_attnWbf[(size_t)LMAX*1024];
__device__ __nv_bfloat16 g_combWbf[(size_t)HID*1024];
__device__ float g_pm[(size_t)MROWS*NCB];
__device__ float g_ps[(size_t)MROWS*NCB];
__device__ float g_tgtlog[MROWS];
__device__ float g_lossp[32];

// distributed-flag grid barrier state
__device__ unsigned g_arr[NBLK];
__device__ unsigned g_rel;

__device__ __forceinline__ float sigmf(float x) { return 1.0f / (1.0f + expf(-x)); }

__device__ __forceinline__ void gridbar(unsigned &gen)
{
    __syncthreads();
    const int tid = threadIdx.x;
    if (blockIdx.x == 0) {
        if (tid > 0 && tid < NBLK) {
            volatile unsigned* a = g_arr + tid;
            while (*a < gen + 1u) { }
        }
        __syncthreads();
        if (tid == 0) {
            __threadfence();
            *(volatile unsigned*)&g_rel = gen + 1u;
        }
    } else {
        if (tid == 0) {
            __threadfence();
            *(volatile unsigned*)&g_arr[blockIdx.x] = gen + 1u;
            volatile unsigned* r = &g_rel;
            while (*r < gen + 1u) { }
        }
    }
    gen++;
    __syncthreads();
}

// ---------------- one-shot fp32 -> bf16 conversion of all eight arrays ----------------
__global__ void k_tobfAll(const float* __restrict__ emb, const float* __restrict__ outW,
                          const float* __restrict__ w0, const float* __restrict__ w1,
                          const float* __restrict__ w2, const float* __restrict__ w3,
                          const float* __restrict__ aw, const float* __restrict__ cw)
{
    int bid = blockIdx.x;
    const float* s;
    __nv_bfloat16* d;
    int base;
    if (bid < 25000) { s = emb; d = g_embbf; base = bid; }
    else if (bid < 50000) { s = outW; d = g_Wobf; base = bid - 25000; }
    else if (bid < 53072) {
        int r = bid - 50000;
        int arr = r / 768;
        base = r % 768;
        s = (arr == 0) ? w0 : (arr == 1) ? w1 : (arr == 2) ? w2 : w3;
        d = (arr == 0) ? g_Wihbf : (arr == 1) ? g_Whhbf : (arr == 2) ? g_dWihbf : g_dWhhbf;
    }
    else if (bid < 53472) { s = aw; d = g_attnWbf; base = bid - 53072; }
    else { s = cw; d = g_combWbf; base = bid - 53472; }
    int i = (base * 256 + threadIdx.x) << 2;
    float4 v = *(const float4*)(s + i);
    *(__nv_bfloat162*)(d + i)     = __floats2bfloat162_rn(v.x, v.y);
    *(__nv_bfloat162*)(d + i + 2) = __floats2bfloat162_rn(v.z, v.w);
}

__global__ void k_init(const int* __restrict__ tgt)
{
    int i = blockIdx.x * 256 + threadIdx.x;
    if (i < BSZ*HID) {
        g_h[i] = 0.0f;
        g_hbf[i] = __float2bfloat16(0.0f);
    }
    if (i < TOUT*BSZ) {
        int t = i / BSZ, b = i % BSZ;
        g_dectok[i] = (t == 0) ? 1 : tgt[(t-1)*BSZ + b];
    }
}

// ================= bf16 WMMA GEMM, 128x128 block, K=512, double-buffered =================
// MODE 0: A row m = Abf[gidx[m]], raw store to Cout (no bias, unguarded 128-col tiles; caller pads).
// MODE 1: A row m = Abf[m], fused bias + streaming logsumexp epilogue.
// ldbB: element stride between B rows (512 for packed, 1024 for attn/comb slices).
template<int MODE>
__global__ void __launch_bounds__(256)
k_wgemm(const __nv_bfloat16* __restrict__ Abf,
        const int* __restrict__ gidx,
        const __nv_bfloat16* __restrict__ Bbf, int ldbB,
        const float* __restrict__ bias,
        float* __restrict__ Cout, int ldC,
        const int* __restrict__ tgt,
        int Ncols)
{
    __shared__ __align__(16) char sbuf[40960];
    float* sC = (float*)sbuf;

    const int tid  = threadIdx.x;
    const int warp = tid >> 5;
    const int rt = warp & 3;
    const int cn = warp >> 2;
    const int bm = blockIdx.y * 128;
    const int bn = blockIdx.x * 128;

    const int cr = tid >> 2;
    const int q8 = (tid & 3) << 3;

    size_t ga0, ga1;
    if (MODE == 0) {
        ga0 = (size_t)gidx[bm + cr]      * KDIM + q8;
        ga1 = (size_t)gidx[bm + cr + 64] * KDIM + q8;
    } else {
        ga0 = (size_t)(bm + cr)      * KDIM + q8;
        ga1 = (size_t)(bm + cr + 64) * KDIM + q8;
    }
    int nb0 = bn + cr;      if (nb0 >= Ncols) nb0 = Ncols - 1;
    int nb1 = bn + cr + 64; if (nb1 >= Ncols) nb1 = Ncols - 1;
    size_t gb0 = (size_t)nb0 * ldbB + q8;
    size_t gb1 = (size_t)nb1 * ldbB + q8;

    const int sa0 = cr*40 + q8;
    const int sa1 = sa0 + 64*40;

    __nv_bfloat16* bufA[2] = { (__nv_bfloat16*)sbuf, (__nv_bfloat16*)(sbuf + 20480) };
    __nv_bfloat16* bufB[2] = { (__nv_bfloat16*)(sbuf + 10240), (__nv_bfloat16*)(sbuf + 30720) };

    uint4 rA0 = *(const uint4*)(Abf + ga0);
    uint4 rA1 = *(const uint4*)(Abf + ga1);
    uint4 rB0 = *(const uint4*)(Bbf + gb0);
    uint4 rB1 = *(const uint4*)(Bbf + gb1);
    *(uint4*)(bufA[0] + sa0) = rA0;
    *(uint4*)(bufA[0] + sa1) = rA1;
    *(uint4*)(bufB[0] + sa0) = rB0;
    *(uint4*)(bufB[0] + sa1) = rB1;
    __syncthreads();

    wmma::fragment<wmma::accumulator, 16, 16, 16, float> fc[2][4];
    for (int mi = 0; mi < 2; mi++)
        for (int ni = 0; ni < 4; ni++)
            wmma::fill_fragment(fc[mi][ni], 0.0f);

    for (int it = 0; it < 16; it++) {
        if (it < 15) {
            int kg = (it + 1) * 32;
            rA0 = *(const uint4*)(Abf + ga0 + kg);
            rA1 = *(const uint4*)(Abf + ga1 + kg);
            rB0 = *(const uint4*)(Bbf + gb0 + kg);
            rB1 = *(const uint4*)(Bbf + gb1 + kg);
        }
        __nv_bfloat16* cA = bufA[it & 1];
        __nv_bfloat16* cB = bufB[it & 1];
        for (int kk = 0; kk < 32; kk += 16) {
            wmma::fragment<wmma::matrix_a, 16, 16, 16, __nv_bfloat16, wmma::row_major> fa[2];
            wmma::fragment<wmma::matrix_b, 16, 16, 16, __nv_bfloat16, wmma::col_major> fb[4];
            wmma::load_matrix_sync(fa[0], cA + (rt*32     )*40 + kk, 40);
            wmma::load_matrix_sync(fa[1], cA + (rt*32 + 16)*40 + kk, 40);
            for (int ni = 0; ni < 4; ni++)
                wmma::load_matrix_sync(fb[ni], cB + (cn*64 + ni*16)*40 + kk, 40);
            for (int mi = 0; mi < 2; mi++)
                for (int ni = 0; ni < 4; ni++)
                    wmma::mma_sync(fc[mi][ni], fa[mi], fb[ni], fc[mi][ni]);
        }
        if (it < 15) {
            __nv_bfloat16* nA = bufA[(it + 1) & 1];
            __nv_bfloat16* nB = bufB[(it + 1) & 1];
            *(uint4*)(nA + sa0) = rA0;
            *(uint4*)(nA + sa1) = rA1;
            *(uint4*)(nB + sa0) = rB0;
            *(uint4*)(nB + sa1) = rB1;
        }
        __syncthreads();
    }

    if (MODE == 0) {
        for (int mi = 0; mi < 2; mi++)
            for (int ni = 0; ni < 4; ni++) {
                size_t row = bm + rt*32 + mi*16;
                int col = bn + cn*64 + ni*16;
                wmma::store_matrix_sync(Cout + row * (size_t)ldC + col,
                                        fc[mi][ni], ldC, wmma::mem_row_major);
            }
    } else {
        const int r  = tid >> 1;
        const int hf = tid & 1;
        const int rg = bm + r;
        const int tv = tgt[rg];
        float Mrun = -1e30f, Srun = 0.0f;

        for (int h = 0; h < 2; h++) {
            if (cn == h) {
                for (int mi = 0; mi < 2; mi++)
                    for (int ni = 0; ni < 4; ni++)
                        wmma::store_matrix_sync(sC + (rt*32 + mi*16)*72 + ni*16,
                                                fc[mi][ni], 72, wmma::mem_row_major);
            }
            __syncthreads();

            float* crow = sC + r*72 + hf*32;
            int cbase = bn + h*64 + hf*32;
            float mx = -1e30f;
            for (int c = 0; c < 32; c++) {
                int gc = cbase + c;
                float v = (gc < Ncols) ? (crow[c] + bias[gc]) : -1e30f;
                crow[c] = v;
                mx = fmaxf(mx, v);
            }
            float s = 0.0f;
            for (int c = 0; c < 32; c++) s += expf(crow[c] - mx);

            float mo = __shfl_xor_sync(0xffffffffu, mx, 1);
            float so = __shfl_xor_sync(0xffffffffu, s,  1);
            float M2 = fmaxf(mx, mo);
            float S2 = s * expf(mx - M2) + so * expf(mo - M2);

            int lc = tv - cbase;
            if (lc >= 0 && lc < 32) g_tgtlog[rg] = crow[lc];

            float nm = fmaxf(Mrun, M2);
            Srun = Srun * expf(Mrun - nm) + S2 * expf(M2 - nm);
            Mrun = nm;
            __syncthreads();
        }
        if (hf == 0) {
            g_pm[(size_t)rg * NCB + blockIdx.x] = Mrun;
            g_ps[(size_t)rg * NCB + blockIdx.x] = Srun;
        }
    }
}

// ---------------- generic fp32 SGEMM (enc0W only) ----------------
template<bool GATHER>
__global__ void __launch_bounds__(256)
k_sgemm128(const float* __restrict__ A,
           const int*  __restrict__ gidx,
           const float* __restrict__ Bw, int ldb,
           const float* __restrict__ bias,
           float* __restrict__ C,
           int M, int N, int K)
{
    __shared__ __align__(16) float sA[16][128];
    __shared__ __align__(16) float sB[16][128];
    const int tid = threadIdx.x;
    const int bm = blockIdx.y * 128;
    const int bn = blockIdx.x * 128;
    const int tx = tid & 15;
    const int ty = tid >> 4;
    const int lr = tid >> 2;
    const int lk = (tid & 3) << 2;

    int m0 = bm + lr, m1 = m0 + 64;
    const bool mv0 = m0 < M, mv1 = m1 < M;
    size_t ar0, ar1;
    if (GATHER) {
        ar0 = (size_t)(mv0 ? gidx[m0] : gidx[0]) * (size_t)K;
        ar1 = (size_t)(mv1 ? gidx[m1] : gidx[0]) * (size_t)K;
    } else {
        ar0 = (size_t)(mv0 ? m0 : 0) * (size_t)K;
        ar1 = (size_t)(mv1 ? m1 : 0) * (size_t)K;
    }
    int n0 = bn + lr, n1 = n0 + 64;
    size_t br0 = (size_t)(n0 < N ? n0 : 0) * (size_t)ldb;
    size_t br1 = (size_t)(n1 < N ? n1 : 0) * (size_t)ldb;

    float acc[8][8];
#pragma unroll
    for (int i = 0; i < 8; i++)
#pragma unroll
        for (int j = 0; j < 8; j++) acc[i][j] = 0.0f;

    for (int kb = 0; kb < K; kb += 16) {
        float4 a0 = *(const float4*)(A  + ar0 + kb + lk);
        float4 a1 = *(const float4*)(A  + ar1 + kb + lk);
        float4 b0 = *(const float4*)(Bw + br0 + kb + lk);
        float4 b1 = *(const float4*)(Bw + br1 + kb + lk);
        __syncthreads();
        sA[lk+0][lr] = a0.x; sA[lk+1][lr] = a0.y; sA[lk+2][lr] = a0.z; sA[lk+3][lr] = a0.w;
        sA[lk+0][lr+64] = a1.x; sA[lk+1][lr+64] = a1.y; sA[lk+2][lr+64] = a1.z; sA[lk+3][lr+64] = a1.w;
        sB[lk+0][lr] = b0.x; sB[lk+1][lr] = b0.y; sB[lk+2][lr] = b0.z; sB[lk+3][lr] = b0.w;
        sB[lk+0][lr+64] = b1.x; sB[lk+1][lr+64] = b1.y; sB[lk+2][lr+64] = b1.z; sB[lk+3][lr+64] = b1.w;
        __syncthreads();
#pragma unroll
        for (int k = 0; k < 16; k++) {
            float4 pa0 = *(const float4*)(&sA[k][ty*8]);
            float4 pa1 = *(const float4*)(&sA[k][ty*8+4]);
            float4 pb0 = *(const float4*)(&sB[k][tx*8]);
            float4 pb1 = *(const float4*)(&sB[k][tx*8+4]);
            float av[8] = {pa0.x, pa0.y, pa0.z, pa0.w, pa1.x, pa1.y, pa1.z, pa1.w};
            float bv[8] = {pb0.x, pb0.y, pb0.z, pb0.w, pb1.x, pb1.y, pb1.z, pb1.w};
#pragma unroll
            for (int i = 0; i < 8; i++)
#pragma unroll
                for (int j = 0; j < 8; j++)
                    acc[i][j] += av[i] * bv[j];
        }
    }

#pragma unroll
    for (int i = 0; i < 8; i++) {
        int m = bm + ty*8 + i;
        if (m < M) {
            float* crow = C + (size_t)m * (size_t)N;
#pragma unroll
            for (int j = 0; j < 8; j++) {
                int n = bn + tx*8 + j;
                if (n < N) crow[n] = acc[i][j] + (bias ? bias[n] : 0.0f);
            }
        }
    }
}

// ---------------- per-task 64x64 WMMA step-GEMM, variable chunk count, double-buffered ----------------
__device__ __forceinline__ void step_wmma_task(
    const __nv_bfloat16* __restrict__ A, const __nv_bfloat16* __restrict__ B,
    int bn, int kbase, int nchunks, float* __restrict__ Cp, char* sbuf)
{
    const int tid  = threadIdx.x;
    const int warp = tid >> 5;
    const int wm = warp >> 2;
    const int wn = warp & 3;
    const int cr = tid >> 2;
    const int q8 = (tid & 3) << 3;

    size_t aoff = (size_t)cr * HID + kbase + q8;
    size_t boff = (size_t)(bn + cr) * HID + kbase + q8;
    const int si = cr*40 + q8;

    __nv_bfloat16* bufA[2] = { (__nv_bfloat16*)sbuf, (__nv_bfloat16*)(sbuf + 10240) };
    __nv_bfloat16* bufB[2] = { (__nv_bfloat16*)(sbuf + 5120), (__nv_bfloat16*)(sbuf + 15360) };

    uint4 ra = *(const uint4*)(A + aoff);
    uint4 rb = *(const uint4*)(B + boff);
    *(uint4*)(bufA[0] + si) = ra;
    *(uint4*)(bufB[0] + si) = rb;
    __syncthreads();

    wmma::fragment<wmma::accumulator,16,16,16,float> fc0, fc1;
    wmma::fill_fragment(fc0, 0.0f);
    wmma::fill_fragment(fc1, 0.0f);

    for (int it = 0; it < nchunks; it++) {
        if (it < nchunks - 1) {
            int kg = (it + 1) * 32;
            ra = *(const uint4*)(A + aoff + kg);
            rb = *(const uint4*)(B + boff + kg);
        }
        __nv_bfloat16* cA = bufA[it & 1];
        __nv_bfloat16* cB = bufB[it & 1];
        for (int kk = 0; kk < 32; kk += 16) {
            wmma::fragment<wmma::matrix_a,16,16,16,__nv_bfloat16,wmma::row_major> fa0, fa1;
            wmma::fragment<wmma::matrix_b,16,16,16,__nv_bfloat16,wmma::col_major> fb;
            wmma::load_matrix_sync(fa0, cA + (wm*32     )*40 + kk, 40);
            wmma::load_matrix_sync(fa1, cA + (wm*32 + 16)*40 + kk, 40);
            wmma::load_matrix_sync(fb,  cB + (wn*16     )*40 + kk, 40);
            wmma::mma_sync(fc0, fa0, fb, fc0);
            wmma::mma_sync(fc1, fa1, fb, fc1);
        }
        if (it < nchunks - 1) {
            __nv_bfloat16* nA = bufA[(it + 1) & 1];
            __nv_bfloat16* nB = bufB[(it + 1) & 1];
            *(uint4*)(nA + si) = ra;
            *(uint4*)(nB + si) = rb;
        }
        __syncthreads();
    }
    wmma::store_matrix_sync(Cp + (size_t)(wm*32     )*G3 + bn + wn*16, fc0, G3, wmma::mem_row_major);
    wmma::store_matrix_sync(Cp + (size_t)(wm*32 + 16)*G3 + bn + wn*16, fc1, G3, wmma::mem_row_major);
}

// ---------------- persistent encoder (148 blocks, 2 barriers/step, K-split 4) ----------------
__global__ void __launch_bounds__(256)
k_encoder(const float* __restrict__ bih, const float* __restrict__ bhh)
{
    __shared__ __align__(16) char sbuf[20480];
    unsigned gen = *(volatile unsigned*)&g_rel;
    const int blk = blockIdx.x;

    for (int t = 0; t < LEN; t++) {
        if (blk < 96) {
            int ks = blk / 24, nb = blk % 24;
            step_wmma_task(g_hbf, g_Whhbf, nb*64, ks*128, 4, g_part + (size_t)ks*BSZ*G3, sbuf);
        }
        gridbar(gen);
        if (blk < 128) {
            int idx = blk*256 + threadIdx.x;
            int b = idx >> 9, j = idx & 511;
            int base = b * G3;
            float hr = bhh[j], hz = bhh[j+512], hn = bhh[j+1024];
#pragma unroll
            for (int s = 0; s < 4; s++) {
                const float* p = g_part + (size_t)s * BSZ * G3 + base;
                hr += p[j]; hz += p[j+512]; hn += p[j+1024];
            }
            const float* gx = g_encGx + ((size_t)t*BSZ + b) * G3;
            float r = sigmf(gx[j] + bih[j] + hr);
            float z = sigmf(gx[j+512] + bih[j+512] + hz);
            float n = tanhf(gx[j+1024] + bih[j+1024] + r * hn);
            float hp = g_h[idx];
            float h2 = (1.0f - z) * n + z * hp;
            g_h[idx] = h2;
            g_hbf[idx] = __float2bfloat16(h2);
            if (t == 0) g_enc0[idx] = h2;
        }
        gridbar(gen);
    }
}

// ---------------- persistent decoder (148 blocks, 3 barriers/step) ----------------
__global__ void __launch_bounds__(256)
k_decoder(const float* __restrict__ attn_b, const float* __restrict__ comb_b,
          const float* __restrict__ attn_W,
          const float* __restrict__ bih, const float* __restrict__ bhh)
{
    __shared__ __align__(16) char sbuf[20480];
    float* sm = (float*)sbuf;
    unsigned gen = *(volatile unsigned*)&g_rel;
    const int blk = blockIdx.x;
    const int tid = threadIdx.x;

    for (int t = 0; t < TOUT; t++) {
        // ---- P1: attention + cfuse for this block's batch (blocks 0..63) ----
        if (blk < 64) {
            const int b = blk;
            float* sh = sm;             // 512
            float* slg = sm + 512;      // 400
            float* sred = sm + 912;     // 256
            float* sa0 = sm + 1168;     // 1
            sh[tid]       = g_h[b*HID + tid];
            sh[tid + 256] = g_h[b*HID + tid + 256];
            __syncthreads();
            const float4* h4 = (const float4*)sh;
            for (int l = tid; l < LMAX; l += 256) {
                const float4* w4 = (const float4*)(attn_W + (size_t)l*1024 + 512);
                float s = 0.0f;
#pragma unroll 4
                for (int k = 0; k < 128; k++) {
                    float4 w = w4[k], h = h4[k];
                    s += w.x*h.x + w.y*h.y + w.z*h.z + w.w*h.w;
                }
                slg[l] = g_attnx[((size_t)t*BSZ + b)*512 + l] + attn_b[l] + s;
            }
            __syncthreads();
            float lm = -1e30f;
            for (int l = tid; l < LMAX; l += 256) lm = fmaxf(lm, slg[l]);
            sred[tid] = lm; __syncthreads();
            for (int off = 128; off > 0; off >>= 1) {
                if (tid < off) sred[tid] = fmaxf(sred[tid], sred[tid+off]);
                __syncthreads();
            }
            float mx = sred[0];
            __syncthreads();
            float ls = 0.0f;
            for (int l = tid; l < LMAX; l += 256) ls += expf(slg[l] - mx);
            sred[tid] = ls; __syncthreads();
            for (int off = 128; off > 0; off >>= 1) {
                if (tid < off) sred[tid] += sred[tid+off];
                __syncthreads();
            }
            if (tid == 0) sa0[0] = expf(slg[0] - mx) / sred[0];
            __syncthreads();
            float a0 = sa0[0];
            for (int j = tid; j < HID; j += 256) {
                float v = g_combx[((size_t)t*BSZ + b)*HID + j] + comb_b[j] + a0 * g_enc0W[b*HID + j];
                g_cbf[b*HID + j] = __float2bfloat16(v > 0.0f ? v : 0.0f);
            }
        }
        gridbar(gen);
        // ---- P2: gate GEMMs ----
        if (blk < 96) {
            int group = blk / 48, rem = blk % 48;
            int ks = rem / 24, nb = rem % 24;
            const __nv_bfloat16* A  = group ? g_hbf : g_cbf;
            const __nv_bfloat16* Bm = group ? g_dWhhbf : g_dWihbf;
            step_wmma_task(A, Bm, nb*64, ks*256, 8,
                           g_part + (size_t)(group*2 + ks)*BSZ*G3, sbuf);
        }
        gridbar(gen);
        // ---- P3: gate fuse ----
        if (blk < 128) {
            int idx = blk*256 + tid;
            int b = idx >> 9, j = idx & 511;
            int base = b * G3;
            float ir = bih[j], iz = bih[j+512], in = bih[j+1024];
            float hr = bhh[j], hz = bhh[j+512], hn = bhh[j+1024];
#pragma unroll
            for (int s = 0; s < 2; s++) {
                const float* pi = g_part + (size_t)s * BSZ * G3 + base;
                const float* ph = g_part + (size_t)(s+2) * BSZ * G3 + base;
                ir += pi[j]; iz += pi[j+512]; in += pi[j+1024];
                hr += ph[j]; hz += ph[j+512]; hn += ph[j+1024];
            }
            float r = sigmf(ir + hr);
            float z = sigmf(iz + hz);
            float n = tanhf(in + r * hn);
            float hp = g_h[idx];
            float h2 = (1.0f - z) * n + z * hp;
            g_h[idx] = h2;
            g_hbf[idx] = __float2bfloat16(h2);
            g_H2bf[(size_t)t*BSZ*HID + idx] = __float2bfloat16(h2);
        }
        gridbar(gen);
    }
}

// ---------------- final logsumexp combine + deterministic loss ----------------
__global__ void k_reduce()
{
    __shared__ float sred[256];
    int m = blockIdx.x * 256 + threadIdx.x;
    const float* pm = g_pm + (size_t)m * NCB;
    const float* ps = g_ps + (size_t)m * NCB;
    float M = pm[0];
    for (int j = 1; j < NCB; j++) M = fmaxf(M, pm[j]);
    float S = 0.0f;
    for (int j = 0; j < NCB; j++) S += ps[j] * expf(pm[j] - M);
    float contrib = (M + logf(S) - g_tgtlog[m]) * (1.0f / 64.0f);
    sred[threadIdx.x] = contrib;
    __syncthreads();
    for (int off = 128; off > 0; off >>= 1) {
        if (threadIdx.x < off) sred[threadIdx.x] += sred[threadIdx.x + off];
        __syncthreads();
    }
    if (threadIdx.x == 0) g_lossp[blockIdx.x] = sred[0];
}

__global__ void k_final(float* __restrict__ out)
{
    float s = 0.0f;
    for (int i = 0; i < 25; i++) s += g_lossp[i];
    out[0] = s;
}

// ---------------- host launcher ----------------
extern "C" void kernel_launch(void* const* d_in, const int* in_sizes, int n_in,
                              void* d_out, int out_size)
{
    const float* emb     = (const float*)d_in[0];
    const float* enc_Wih = (const float*)d_in[1];
    const float* enc_Whh = (const float*)d_in[2];
    const float* enc_bih = (const float*)d_in[3];
    const float* enc_bhh = (const float*)d_in[4];
    const float* attn_W  = (const float*)d_in[5];
    const float* attn_b  = (const float*)d_in[6];
    const float* comb_W  = (const float*)d_in[7];
    const float* comb_b  = (const float*)d_in[8];
    const float* dec_Wih = (const float*)d_in[9];
    const float* dec_Whh = (const float*)d_in[10];
    const float* dec_bih = (const float*)d_in[11];
    const float* dec_bhh = (const float*)d_in[12];
    const float* out_W   = (const float*)d_in[13];
    const float* out_b   = (const float*)d_in[14];
    const int*   in_tok  = (const int*)d_in[15];
    const int*   tgt     = (const int*)d_in[16];

    float *p_attnx, *p_combx, *p_enc0, *p_enc0W, *p_encGx;
    int *p_dectok;
    __nv_bfloat16 *p_embbf, *p_Wobf, *p_Wihbf, *p_H2bf, *p_attnWbf, *p_combWbf;
    cudaGetSymbolAddress((void**)&p_encGx, g_encGx);
    cudaGetSymbolAddress((void**)&p_attnx, g_attnx);
    cudaGetSymbolAddress((void**)&p_combx, g_combx);
    cudaGetSymbolAddress((void**)&p_enc0,  g_enc0);
    cudaGetSymbolAddress((void**)&p_enc0W, g_enc0W);
    cudaGetSymbolAddress((void**)&p_dectok, g_dectok);
    cudaGetSymbolAddress((void**)&p_embbf, g_embbf);
    cudaGetSymbolAddress((void**)&p_Wobf,  g_Wobf);
    cudaGetSymbolAddress((void**)&p_Wihbf, g_Wihbf);
    cudaGetSymbolAddress((void**)&p_H2bf,  g_H2bf);
    cudaGetSymbolAddress((void**)&p_attnWbf, g_attnWbf);
    cudaGetSymbolAddress((void**)&p_combWbf, g_combWbf);

    // launch order: wgemm<0> (encGx) is launch index 2 -> captured by ncu
    k_init<<<128, 256>>>(tgt);                                                   // 0
    k_tobfAll<<<53984, 256>>>(emb, out_W, enc_Wih, enc_Whh, dec_Wih, dec_Whh,    // 1
                              attn_W, comb_W);
    k_wgemm<0><<<dim3(12, 200), 256>>>(p_embbf, in_tok, p_Wihbf, KDIM,           // 2 <- profiled
                                       (const float*)0, p_encGx, G3,
                                       (const int*)0, G3);
    k_wgemm<0><<<dim3(4, 50), 256>>>(p_embbf, p_dectok, p_attnWbf, 1024,         // 3 (attnx, N=400 padded)
                                     (const float*)0, p_attnx, 512,
                                     (const int*)0, LMAX);
    k_wgemm<0><<<dim3(4, 50), 256>>>(p_embbf, p_dectok, p_combWbf, 1024,         // 4 (combx)
                                     (const float*)0, p_combx, HID,
                                     (const int*)0, HID);
    k_encoder<<<NBLK, 256>>>(enc_bih, enc_bhh);                                  // 5

    k_sgemm128<false><<<dim3(4, 1), 256>>>(p_enc0, (const int*)0, comb_W + 512, 1024,
                                           (const float*)0, p_enc0W, BSZ, HID, HID);
    k_decoder<<<NBLK, 256>>>(attn_b, comb_b, attn_W, dec_bih, dec_bhh);
    k_wgemm<1><<<dim3(NCB, 50), 256>>>(p_H2bf, (const int*)0, p_Wobf, KDIM, out_b,
                                       (float*)0, 0, tgt, VOC);
    k_reduce<<<25, 256>>>();
    k_final<<<1, 1>>>((float*)d_out);
}